// round 12
// baseline (speedup 1.0000x reference)
#include <cuda_runtime.h>

// ---------------------------------------------------------------------------
// QuantumNet, fully collapsed via Heisenberg propagation of Z0.
//
//   out = 0.5 + ha*cos(x0) + hb*sin(x0)
//
// O = U^H Z0 U stays in span{Z0, Y0, Z0X1, Y0X1} for any layer count
// (CNOT: Y0<->Y0X1; RX1: identity on the span; RX0 rotates (z,y) pairs).
// On the encoded state <Z0>=cos x0, <Y0>=-sin x0, all X1 terms vanish:
// x1 and the RX1 weights are irrelevant. (Validated R8/R10/R11: ~1e-7.)
//
// Scheduling (the actual fix this round): the per-SM L1tex queue completes
// loads in ISSUE order. Weight loads must therefore be issued BEFORE the
// bulk x loads, or they complete behind hundreds of queued x wavefronts and
// stall the whole epilogue (the ~2.5us penalty of R8/R10/R11). Order here:
//   1) <=8 predicated uniform LDG.32 of RX0 weights   (queue FRONT)
//   2) 4x LDG.128 of x (front-batched, MLP=4)
//   3) fully-unrolled register recurrence (hidden under x latency)
//   4) 8x (sincos + 2 FMA) + 2x STG.128
// No barrier, no smem, single launch.
// ---------------------------------------------------------------------------

#define MAXL 8   // compile-time cap on layers handled by the fast path

__global__ void __launch_bounds__(256)
qnet_kernel(const float* __restrict__ x, float* __restrict__ out, int n,
            const float* __restrict__ w, int n_layers) {
    long long t = (long long)blockIdx.x * blockDim.x + threadIdx.x;
    long long base = t * 8;                    // 8 samples per thread
    const bool full = (base + 7) < (long long)n;

    // ---- 1) Weight loads FIRST (front of the L1tex FIFO) -----------------
    float wl[MAXL];
#pragma unroll
    for (int l = 0; l < MAXL; l++)
        wl[l] = (l < n_layers) ? __ldg(w + 2 * l) : 0.0f;

    // ---- 2) Front-batched x loads: 4x LDG.128 (MLP=4) --------------------
    float4 a, b, c, d;
    if (full) {
        const float4* x4 = (const float4*)x;
        a = x4[t * 4 + 0];                     // (x0_0, x1_0, x0_1, x1_1)
        b = x4[t * 4 + 1];
        c = x4[t * 4 + 2];
        d = x4[t * 4 + 3];
    }

    // ---- 3) Recurrence on registers, unrolled (hidden under x latency) ---
    float z = 1.0f, y = 0.0f, zx = 0.0f, yx = 0.0f;
#pragma unroll
    for (int l = MAXL - 1; l >= 0; l--) {
        if (l < n_layers) {
            float tmp = y; y = yx; yx = tmp;   // CNOT: Y0 <-> Y0X1
            float s, cc;
            __sincosf(wl[l], &s, &cc);         // RX0(w_l0) conjugation
            float z2  = fmaf(cc, z,  -s * y);
            float y2  = fmaf(s,  z,   cc * y);
            float zx2 = fmaf(cc, zx, -s * yx);
            float yx2 = fmaf(s,  zx,  cc * yx);
            z = z2; y = y2; zx = zx2; yx = yx2;
        }
    }
    const float ha = 0.5f * z;                 // coeff of cos(x0)
    const float hb = -0.5f * y;                // coeff of sin(x0)

    // ---- 4) Consume: sincos + 2 FMA per sample ---------------------------
    if (full) {
        float S, C;
        float4 o0, o1;
        __sincosf(a.x, &S, &C); o0.x = fmaf(ha, C, fmaf(hb, S, 0.5f));
        __sincosf(a.z, &S, &C); o0.y = fmaf(ha, C, fmaf(hb, S, 0.5f));
        __sincosf(b.x, &S, &C); o0.z = fmaf(ha, C, fmaf(hb, S, 0.5f));
        __sincosf(b.z, &S, &C); o0.w = fmaf(ha, C, fmaf(hb, S, 0.5f));
        __sincosf(c.x, &S, &C); o1.x = fmaf(ha, C, fmaf(hb, S, 0.5f));
        __sincosf(c.z, &S, &C); o1.y = fmaf(ha, C, fmaf(hb, S, 0.5f));
        __sincosf(d.x, &S, &C); o1.z = fmaf(ha, C, fmaf(hb, S, 0.5f));
        __sincosf(d.z, &S, &C); o1.w = fmaf(ha, C, fmaf(hb, S, 0.5f));
        float4* out4 = (float4*)out;
        out4[t * 2 + 0] = o0;
        out4[t * 2 + 1] = o1;
    } else {
        for (long long i = base; i < (long long)n; i++) {
            float S, C;
            __sincosf(x[2 * i], &S, &C);
            out[i] = fmaf(ha, C, fmaf(hb, S, 0.5f));
        }
    }
}

// Generic fallback for n_layers > MAXL (never taken for this problem's
// N_LAYERS=2, but keeps the kernel correct for any layer count).
__global__ void __launch_bounds__(256)
qnet_kernel_generic(const float* __restrict__ x, float* __restrict__ out,
                    int n, const float* __restrict__ w, int n_layers) {
    float z = 1.0f, y = 0.0f, zx = 0.0f, yx = 0.0f;
    for (int l = n_layers - 1; l >= 0; l--) {
        float tmp = y; y = yx; yx = tmp;
        float s, cc;
        __sincosf(__ldg(w + 2 * l), &s, &cc);
        float z2  = fmaf(cc, z,  -s * y);
        float y2  = fmaf(s,  z,   cc * y);
        float zx2 = fmaf(cc, zx, -s * yx);
        float yx2 = fmaf(s,  zx,  cc * yx);
        z = z2; y = y2; zx = zx2; yx = yx2;
    }
    const float ha = 0.5f * z, hb = -0.5f * y;
    long long i = (long long)blockIdx.x * blockDim.x + threadIdx.x;
    if (i < (long long)n) {
        float S, C;
        __sincosf(x[2 * i], &S, &C);
        out[i] = fmaf(ha, C, fmaf(hb, S, 0.5f));
    }
}

extern "C" void kernel_launch(void* const* d_in, const int* in_sizes, int n_in,
                              void* d_out, int out_size) {
    const float* x = (const float*)d_in[0];    // [B, 2] float32
    const float* w = (const float*)d_in[1];    // [N_LAYERS, 2] float32
    float* out = (float*)d_out;                // [B, 1] float32

    int n = in_sizes[0] / 2;                   // samples B
    int n_layers = in_sizes[1] / 2;

    if (n_layers <= MAXL) {
        long long threads = ((long long)n + 7) / 8;
        int blocks = (int)((threads + 255) / 256);
        qnet_kernel<<<blocks, 256>>>(x, out, n, w, n_layers);
    } else {
        int blocks = (int)(((long long)n + 255) / 256);
        qnet_kernel_generic<<<blocks, 256>>>(x, out, n, w, n_layers);
    }
}

// round 13
// speedup vs baseline: 1.6821x; 1.6821x over previous
#include <cuda_runtime.h>

// ---------------------------------------------------------------------------
// QuantumNet, fully collapsed via Heisenberg propagation of Z0.
//
//   out = 0.5 + ha*cos(x0) + hb*sin(x0)
//
// O = U^H Z0 U stays in span{Z0, Y0, Z0X1, Y0X1} for any layer count
// (CNOT: Y0<->Y0X1; RX1: identity on the span; RX0 rotates (z,y) pairs).
// On the encoded state <Z0>=cos x0, <Y0>=-sin x0, all X1 terms vanish:
// x1 and the RX1 weights are irrelevant. (Validated R8-R12: rel_err ~1e-7.)
//
// R13 fix — WARP-COALESCED layout. Previous rounds gave each thread 4
// consecutive float4s: every warp-wide LDG.128 strided 64B across lanes,
// touching 16 cache lines instead of 4 (L1tex 61% busy = the real plateau).
// Now warp W owns float4 indices [W*128, W*128+128); lane l takes
// W*128 + k*32 + l, k=0..3. Every LDG.128 is 512B contiguous (4 wavefronts,
// minimum); each input float4 maps to out2[] at the SAME index, so stores
// are lane-consecutive STG.64 (2 wavefronts). 24 wavefronts/warp vs 80.
// ---------------------------------------------------------------------------

#define MAXL 8   // compile-time cap on layers handled by the fast path

__global__ void __launch_bounds__(256)
qnet_kernel(const float4* __restrict__ x4, float2* __restrict__ out2, int m,
            const float* __restrict__ w, int n_layers) {
    // m = number of float4s in x (= n/2); every float4 -> one float2 out.
    int t = blockIdx.x * blockDim.x + threadIdx.x;
    long long base = (long long)(t >> 5) * 128 + (t & 31);

    // ---- 1) Weight loads first (uniform, L2-resident broadcast) ----------
    float wl[MAXL];
#pragma unroll
    for (int l = 0; l < MAXL; l++)
        wl[l] = (l < n_layers) ? __ldg(w + 2 * l) : 0.0f;

    // ---- 2) 4 fully-coalesced LDG.128 (4 wavefronts each, MLP=4) ---------
    const bool full = (base + 96) < (long long)m;
    float4 v0, v1, v2, v3;
    if (full) {
        v0 = x4[base +  0];
        v1 = x4[base + 32];
        v2 = x4[base + 64];
        v3 = x4[base + 96];
    }

    // ---- 3) Unrolled register recurrence (hidden under load latency) -----
    float z = 1.0f, y = 0.0f, zx = 0.0f, yx = 0.0f;
#pragma unroll
    for (int l = MAXL - 1; l >= 0; l--) {
        if (l < n_layers) {
            float tmp = y; y = yx; yx = tmp;   // CNOT: Y0 <-> Y0X1
            float s, cc;
            __sincosf(wl[l], &s, &cc);         // RX0(w_l0) conjugation
            float z2  = fmaf(cc, z,  -s * y);
            float y2  = fmaf(s,  z,   cc * y);
            float zx2 = fmaf(cc, zx, -s * yx);
            float yx2 = fmaf(s,  zx,  cc * yx);
            z = z2; y = y2; zx = zx2; yx = yx2;
        }
    }
    const float ha = 0.5f * z;                 // coeff of cos(x0)
    const float hb = -0.5f * y;                // coeff of sin(x0)

    // ---- 4) Consume: each float4 = 2 samples -> one float2 ---------------
    if (full) {
        float S, C;
        float2 r0, r1, r2, r3;
        __sincosf(v0.x, &S, &C); r0.x = fmaf(ha, C, fmaf(hb, S, 0.5f));
        __sincosf(v0.z, &S, &C); r0.y = fmaf(ha, C, fmaf(hb, S, 0.5f));
        __sincosf(v1.x, &S, &C); r1.x = fmaf(ha, C, fmaf(hb, S, 0.5f));
        __sincosf(v1.z, &S, &C); r1.y = fmaf(ha, C, fmaf(hb, S, 0.5f));
        __sincosf(v2.x, &S, &C); r2.x = fmaf(ha, C, fmaf(hb, S, 0.5f));
        __sincosf(v2.z, &S, &C); r2.y = fmaf(ha, C, fmaf(hb, S, 0.5f));
        __sincosf(v3.x, &S, &C); r3.x = fmaf(ha, C, fmaf(hb, S, 0.5f));
        __sincosf(v3.z, &S, &C); r3.y = fmaf(ha, C, fmaf(hb, S, 0.5f));
        // lane-consecutive STG.64 at the SAME indices as the loads
        out2[base +  0] = r0;
        out2[base + 32] = r1;
        out2[base + 64] = r2;
        out2[base + 96] = r3;
    } else {
        // tail: scalar per-float4 handling
        const long long idx[4] = { base, base + 32, base + 64, base + 96 };
#pragma unroll
        for (int k = 0; k < 4; k++) {
            if (idx[k] < (long long)m) {
                float4 v = x4[idx[k]];
                float S, C;
                float2 r;
                __sincosf(v.x, &S, &C); r.x = fmaf(ha, C, fmaf(hb, S, 0.5f));
                __sincosf(v.z, &S, &C); r.y = fmaf(ha, C, fmaf(hb, S, 0.5f));
                out2[idx[k]] = r;
            }
        }
    }
}

// Scalar fallback: n not divisible by 4 samples (x not float4-aligned count)
// or n_layers > MAXL. Never taken for this problem (B=4.19M, N_LAYERS=2).
__global__ void __launch_bounds__(256)
qnet_kernel_generic(const float* __restrict__ x, float* __restrict__ out,
                    int n, const float* __restrict__ w, int n_layers) {
    float z = 1.0f, y = 0.0f, zx = 0.0f, yx = 0.0f;
    for (int l = n_layers - 1; l >= 0; l--) {
        float tmp = y; y = yx; yx = tmp;
        float s, cc;
        __sincosf(__ldg(w + 2 * l), &s, &cc);
        float z2  = fmaf(cc, z,  -s * y);
        float y2  = fmaf(s,  z,   cc * y);
        float zx2 = fmaf(cc, zx, -s * yx);
        float yx2 = fmaf(s,  zx,  cc * yx);
        z = z2; y = y2; zx = zx2; yx = yx2;
    }
    const float ha = 0.5f * z, hb = -0.5f * y;
    long long i = (long long)blockIdx.x * blockDim.x + threadIdx.x;
    if (i < (long long)n) {
        float S, C;
        __sincosf(x[2 * i], &S, &C);
        out[i] = fmaf(ha, C, fmaf(hb, S, 0.5f));
    }
}

extern "C" void kernel_launch(void* const* d_in, const int* in_sizes, int n_in,
                              void* d_out, int out_size) {
    const float* x = (const float*)d_in[0];    // [B, 2] float32
    const float* w = (const float*)d_in[1];    // [N_LAYERS, 2] float32
    float* out = (float*)d_out;                // [B, 1] float32

    int n = in_sizes[0] / 2;                   // samples B
    int n_layers = in_sizes[1] / 2;

    if ((n % 4) == 0 && n_layers <= MAXL) {
        int m = n / 2;                         // float4 count (2 samples each)
        long long threads = ((long long)m + 3) / 4;
        int blocks = (int)((threads + 255) / 256);
        qnet_kernel<<<blocks, 256>>>((const float4*)x, (float2*)out, m,
                                     w, n_layers);
    } else {
        int blocks = (int)(((long long)n + 255) / 256);
        qnet_kernel_generic<<<blocks, 256>>>(x, out, n, w, n_layers);
    }
}

// round 14
// speedup vs baseline: 1.6882x; 1.0036x over previous
#include <cuda_runtime.h>

// ---------------------------------------------------------------------------
// QuantumNet, fully collapsed via Heisenberg propagation of Z0.
//
//   out = 0.5 + ha*cos(x0) + hb*sin(x0)
//
// O = U^H Z0 U stays in span{Z0, Y0, Z0X1, Y0X1} for any layer count
// (CNOT: Y0<->Y0X1; RX1: identity on the span; RX0 rotates (z,y) pairs).
// On the encoded state <Z0>=cos x0, <Y0>=-sin x0, all X1 terms vanish:
// x1 and the RX1 weights are irrelevant. (Validated R8-R13: rel_err ~1e-7.)
//
// R13 proved the layout: warp-coalesced float4 ownership (lane-consecutive
// LDG.128 = 4 wavefronts, the minimum; L1 61%->29%, 13.4->10.2us).
// R14: latency-bound per ncu (DRAM 41.8%, issue 31%) -> double per-thread
// MLP to 8 front-batched LDG.128 (16 samples/thread, 256 float4s per warp),
// and all-int32 indexing to kill the IMAD.WIDE chains (alu 7.4%).
// ---------------------------------------------------------------------------

#define MAXL 8   // compile-time cap on layers handled by the fast path

__global__ void __launch_bounds__(256)
qnet_kernel(const float4* __restrict__ x4, float2* __restrict__ out2, int m,
            const float* __restrict__ w, int n_layers) {
    // m = number of float4s (= n/2). Warp owns 256 consecutive float4s;
    // lane l handles base + k*32 + l for k = 0..7.
    int t = blockIdx.x * blockDim.x + threadIdx.x;
    int base = (t >> 5) * 256 + (t & 31);

    // ---- 1) Weight loads first (uniform, broadcast) ----------------------
    float wl[MAXL];
#pragma unroll
    for (int l = 0; l < MAXL; l++)
        wl[l] = (l < n_layers) ? __ldg(w + 2 * l) : 0.0f;

    // ---- 2) 8 front-batched, fully-coalesced LDG.128 (MLP=8) -------------
    const bool full = (base + 224) < m;
    float4 v[8];
    if (full) {
#pragma unroll
        for (int k = 0; k < 8; k++)
            v[k] = x4[base + k * 32];
    }

    // ---- 3) Unrolled register recurrence (hidden under load latency) -----
    float z = 1.0f, y = 0.0f, zxp = 0.0f, yxp = 0.0f;
#pragma unroll
    for (int l = MAXL - 1; l >= 0; l--) {
        if (l < n_layers) {
            float tmp = y; y = yxp; yxp = tmp;  // CNOT: Y0 <-> Y0X1
            float s, cc;
            __sincosf(wl[l], &s, &cc);          // RX0(w_l0) conjugation
            float z2  = fmaf(cc, z,   -s * y);
            float y2  = fmaf(s,  z,    cc * y);
            float zx2 = fmaf(cc, zxp, -s * yxp);
            float yx2 = fmaf(s,  zxp,  cc * yxp);
            z = z2; y = y2; zxp = zx2; yxp = yx2;
        }
    }
    const float ha = 0.5f * z;                  // coeff of cos(x0)
    const float hb = -0.5f * y;                 // coeff of sin(x0)

    // ---- 4) Consume: each float4 = 2 samples -> one float2 ---------------
    if (full) {
#pragma unroll
        for (int k = 0; k < 8; k++) {
            float S, C;
            float2 r;
            __sincosf(v[k].x, &S, &C); r.x = fmaf(ha, C, fmaf(hb, S, 0.5f));
            __sincosf(v[k].z, &S, &C); r.y = fmaf(ha, C, fmaf(hb, S, 0.5f));
            out2[base + k * 32] = r;            // lane-consecutive STG.64
        }
    } else {
#pragma unroll
        for (int k = 0; k < 8; k++) {
            int idx = base + k * 32;
            if (idx < m) {
                float4 vv = x4[idx];
                float S, C;
                float2 r;
                __sincosf(vv.x, &S, &C); r.x = fmaf(ha, C, fmaf(hb, S, 0.5f));
                __sincosf(vv.z, &S, &C); r.y = fmaf(ha, C, fmaf(hb, S, 0.5f));
                out2[idx] = r;
            }
        }
    }
}

// Scalar fallback: odd shapes or n_layers > MAXL. Never taken here
// (B = 4.19M, N_LAYERS = 2).
__global__ void __launch_bounds__(256)
qnet_kernel_generic(const float* __restrict__ x, float* __restrict__ out,
                    int n, const float* __restrict__ w, int n_layers) {
    float z = 1.0f, y = 0.0f, zxp = 0.0f, yxp = 0.0f;
    for (int l = n_layers - 1; l >= 0; l--) {
        float tmp = y; y = yxp; yxp = tmp;
        float s, cc;
        __sincosf(__ldg(w + 2 * l), &s, &cc);
        float z2  = fmaf(cc, z,   -s * y);
        float y2  = fmaf(s,  z,    cc * y);
        float zx2 = fmaf(cc, zxp, -s * yxp);
        float yx2 = fmaf(s,  zxp,  cc * yxp);
        z = z2; y = y2; zxp = zx2; yxp = yx2;
    }
    const float ha = 0.5f * z, hb = -0.5f * y;
    long long i = (long long)blockIdx.x * blockDim.x + threadIdx.x;
    if (i < (long long)n) {
        float S, C;
        __sincosf(x[2 * i], &S, &C);
        out[i] = fmaf(ha, C, fmaf(hb, S, 0.5f));
    }
}

extern "C" void kernel_launch(void* const* d_in, const int* in_sizes, int n_in,
                              void* d_out, int out_size) {
    const float* x = (const float*)d_in[0];    // [B, 2] float32
    const float* w = (const float*)d_in[1];    // [N_LAYERS, 2] float32
    float* out = (float*)d_out;                // [B, 1] float32

    int n = in_sizes[0] / 2;                   // samples B
    int n_layers = in_sizes[1] / 2;

    if ((n % 4) == 0 && n_layers <= MAXL) {
        int m = n / 2;                         // float4 count (2 samples each)
        long long threads = ((long long)m + 7) / 8;
        int blocks = (int)((threads + 255) / 256);
        qnet_kernel<<<blocks, 256>>>((const float4*)x, (float2*)out, m,
                                     w, n_layers);
    } else {
        int blocks = (int)(((long long)n + 255) / 256);
        qnet_kernel_generic<<<blocks, 256>>>(x, out, n, w, n_layers);
    }
}

// round 15
// speedup vs baseline: 1.7380x; 1.0295x over previous
#include <cuda_runtime.h>

// ---------------------------------------------------------------------------
// QuantumNet, fully collapsed via Heisenberg propagation of Z0.
//
//   out = 0.5 + ha*cos(x0) + hb*sin(x0)
//
// O = U^H Z0 U stays in span{Z0, Y0, Z0X1, Y0X1} for any layer count
// (CNOT: Y0<->Y0X1; RX1: identity on the span; RX0 rotates (z,y) pairs).
// On the encoded state <Z0>=cos x0, <Y0>=-sin x0, all X1 terms vanish:
// x1 and the RX1 weights are irrelevant. (Validated R8-R14: rel_err ~1e-7.)
//
// R15: software-pipelined double buffer. Each warp owns exactly 2 chunks of
// 128 consecutive float4s (lane-coalesced: 4-wavefront LDG.128, the R13 win).
// Chunk 1's loads are issued BEFORE chunk 0 is computed, so the second
// latency is hidden under the first chunk's sincos+stores. Grid = 1024 CTAs
// (one balanced wave, no 1.73-wave tail).
// ---------------------------------------------------------------------------

#define MAXL 8   // compile-time cap on layers handled by the fast path

__device__ __forceinline__ void consume_chunk(const float4 v[4], int b,
                                              float2* __restrict__ out2,
                                              float ha, float hb) {
#pragma unroll
    for (int k = 0; k < 4; k++) {
        float S, C;
        float2 r;
        __sincosf(v[k].x, &S, &C); r.x = fmaf(ha, C, fmaf(hb, S, 0.5f));
        __sincosf(v[k].z, &S, &C); r.y = fmaf(ha, C, fmaf(hb, S, 0.5f));
        out2[b + k * 32] = r;                  // lane-consecutive STG.64
    }
}

__global__ void __launch_bounds__(256)
qnet_kernel(const float4* __restrict__ x4, float2* __restrict__ out2,
            int nchunks, const float* __restrict__ w, int n_layers) {
    int t = blockIdx.x * blockDim.x + threadIdx.x;
    int warp = t >> 5;
    int lane = t & 31;
    int nwarps = (gridDim.x * blockDim.x) >> 5;

    // ---- 1) Weight loads first (uniform broadcast) -----------------------
    float wl[MAXL];
#pragma unroll
    for (int l = 0; l < MAXL; l++)
        wl[l] = (l < n_layers) ? __ldg(w + 2 * l) : 0.0f;

    // ---- 2) Chunk 0 loads: 4 coalesced LDG.128 (front of pipeline) -------
    int c0 = warp;                             // first chunk for this warp
    int b0 = c0 * 128 + lane;
    float4 v0[4];
    const bool h0 = c0 < nchunks;
    if (h0) {
#pragma unroll
        for (int k = 0; k < 4; k++) v0[k] = x4[b0 + k * 32];
    }

    // ---- 3) Chunk 1 loads issued BEFORE chunk-0 compute ------------------
    int c1 = warp + nwarps;                    // second chunk
    int b1 = c1 * 128 + lane;
    float4 v1[4];
    const bool h1 = c1 < nchunks;
    if (h1) {
#pragma unroll
        for (int k = 0; k < 4; k++) v1[k] = x4[b1 + k * 32];
    }

    // ---- 4) Recurrence on registers (hidden under load latency) ----------
    float z = 1.0f, y = 0.0f, zxp = 0.0f, yxp = 0.0f;
#pragma unroll
    for (int l = MAXL - 1; l >= 0; l--) {
        if (l < n_layers) {
            float tmp = y; y = yxp; yxp = tmp;  // CNOT: Y0 <-> Y0X1
            float s, cc;
            __sincosf(wl[l], &s, &cc);          // RX0(w_l0) conjugation
            float z2  = fmaf(cc, z,   -s * y);
            float y2  = fmaf(s,  z,    cc * y);
            float zx2 = fmaf(cc, zxp, -s * yxp);
            float yx2 = fmaf(s,  zxp,  cc * yxp);
            z = z2; y = y2; zxp = zx2; yxp = yx2;
        }
    }
    const float ha = 0.5f * z;                 // coeff of cos(x0)
    const float hb = -0.5f * y;                // coeff of sin(x0)

    // ---- 5) Compute/store chunk 0 (chunk 1 still in flight), then 1 ------
    if (h0) consume_chunk(v0, b0, out2, ha, hb);
    if (h1) consume_chunk(v1, b1, out2, ha, hb);
}

// Scalar fallback: odd shapes or n_layers > MAXL. Never taken here
// (B = 4.19M, N_LAYERS = 2).
__global__ void __launch_bounds__(256)
qnet_kernel_generic(const float* __restrict__ x, float* __restrict__ out,
                    int n, const float* __restrict__ w, int n_layers) {
    float z = 1.0f, y = 0.0f, zxp = 0.0f, yxp = 0.0f;
    for (int l = n_layers - 1; l >= 0; l--) {
        float tmp = y; y = yxp; yxp = tmp;
        float s, cc;
        __sincosf(__ldg(w + 2 * l), &s, &cc);
        float z2  = fmaf(cc, z,   -s * y);
        float y2  = fmaf(s,  z,    cc * y);
        float zx2 = fmaf(cc, zxp, -s * yxp);
        float yx2 = fmaf(s,  zxp,  cc * yxp);
        z = z2; y = y2; zxp = zx2; yxp = yx2;
    }
    const float ha = 0.5f * z, hb = -0.5f * y;
    long long i = (long long)blockIdx.x * blockDim.x + threadIdx.x;
    if (i < (long long)n) {
        float S, C;
        __sincosf(x[2 * i], &S, &C);
        out[i] = fmaf(ha, C, fmaf(hb, S, 0.5f));
    }
}

extern "C" void kernel_launch(void* const* d_in, const int* in_sizes, int n_in,
                              void* d_out, int out_size) {
    const float* x = (const float*)d_in[0];    // [B, 2] float32
    const float* w = (const float*)d_in[1];    // [N_LAYERS, 2] float32
    float* out = (float*)d_out;                // [B, 1] float32

    int n = in_sizes[0] / 2;                   // samples B
    int n_layers = in_sizes[1] / 2;

    // Fast path: n divisible by 256 samples (chunks of 128 float4s) and
    // layer count within the unrolled cap.
    if ((n % 256) == 0 && n_layers <= MAXL) {
        int m = n / 2;                         // float4 count
        int nchunks = m / 128;                 // 128 float4s per warp-chunk
        int warps = (nchunks + 1) / 2;         // 2 chunks per warp
        int blocks = (warps * 32 + 255) / 256;
        qnet_kernel<<<blocks, 256>>>((const float4*)x, (float2*)out,
                                     nchunks, w, n_layers);
    } else {
        int blocks = (int)(((long long)n + 255) / 256);
        qnet_kernel_generic<<<blocks, 256>>>(x, out, n, w, n_layers);
    }
}